// round 16
// baseline (speedup 1.0000x reference)
#include <cuda_runtime.h>
#include <cuda_fp16.h>

#define NBLOCKS 128
#define NT 1024
typedef unsigned long long ull;

__device__ __align__(16) __half g_xh [1024*256];     // gathered embeddings (half)
__device__ __align__(16) float  g_io [1024*768];     // shift|scale|proj_x (fp32)
__device__ __align__(16) float  g_part[16*8*64*256]; // [b][rel][j][d] partial lin_sum
__device__ __align__(16) __half g_hh [1024*256];     // recurrent state (half)
__device__ __align__(16) __half g_wpH [2048*256];    // Wp  transposed [n][k] half
__device__ __align__(16) __half g_winH[768*256];     // Win transposed [n][k] half
__device__ __align__(16) __half g_woH [256*256];     // Wout transposed [n][k] half
__device__ int g_len[16];
__device__ unsigned g_cnt = 0, g_gen = 0;
__device__ unsigned g_gcnt[16*32];
__device__ unsigned g_ggen[16*32];

// ---------- helpers ----------
__device__ __forceinline__ void cpa16(void* s, const void* g){
    unsigned ss = (unsigned)__cvta_generic_to_shared(s);
    asm volatile("cp.async.cg.shared.global [%0], [%1], 16;\n" :: "r"(ss), "l"(g));
}
#define CPA_COMMIT() asm volatile("cp.async.commit_group;\n" ::: "memory")
#define CPA_WAIT0()  asm volatile("cp.async.wait_group 0;\n" ::: "memory")
#define CPA_WAIT1()  asm volatile("cp.async.wait_group 1;\n" ::: "memory")

// legacy HMMA m16n8k16 fp16, fp32 accumulate
__device__ __forceinline__ void mma_f16(float* d, const unsigned* a, const unsigned* b){
    asm volatile(
        "mma.sync.aligned.m16n8k16.row.col.f32.f16.f16.f32 "
        "{%0,%1,%2,%3}, {%4,%5,%6,%7}, {%8,%9}, {%0,%1,%2,%3};"
        : "+f"(d[0]), "+f"(d[1]), "+f"(d[2]), "+f"(d[3])
        : "r"(a[0]), "r"(a[1]), "r"(a[2]), "r"(a[3]), "r"(b[0]), "r"(b[1]));
}

// ---------- dynamic smem layout (bytes) ----------
#define OFF_A    135168
#define OFF_P    168960
#define OFF_ASE  205824
#define SMEM_DYN 215040
struct StepSm { __half hsmh[16][264]; float lnp[8][4][2]; };

// ---------- lightweight acq/rel barriers ----------
__device__ __forceinline__ void bar_lite(unsigned* cnt, unsigned* gen, unsigned last){
    __syncthreads();
    if (threadIdx.x == 0){
        unsigned my, old;
        asm volatile("ld.relaxed.gpu.u32 %0, [%1];" : "=r"(my) : "l"(gen) : "memory");
        asm volatile("atom.add.acq_rel.gpu.u32 %0, [%1], 1;" : "=r"(old) : "l"(cnt) : "memory");
        if (old == last){
            asm volatile("st.relaxed.gpu.u32 [%0], 0;" :: "l"(cnt) : "memory");
            unsigned du;
            asm volatile("atom.add.release.gpu.u32 %0, [%1], 1;" : "=r"(du) : "l"(gen) : "memory");
        } else {
            unsigned v;
            do {
                asm volatile("ld.acquire.gpu.u32 %0, [%1];" : "=r"(v) : "l"(gen) : "memory");
            } while (v == my);
        }
        __threadfence();   // CCTL.IVALL — invalidate this SM's L1D
    }
    __syncthreads();
}
__device__ __forceinline__ void grid_sync(){ bar_lite(&g_cnt, &g_gen, NBLOCKS - 1u); }
__device__ __forceinline__ void group_sync(int b){ bar_lite(&g_gcnt[b*32], &g_ggen[b*32], 7u); }

// ---------- stage persistent B slice (256 n x 256 k half) ----------
__device__ void stage_B(const __half* __restrict__ BsrcT, int n0, char* dyn){
    __half* Bsm = (__half*)dyn;
    const int t = threadIdx.x;
    #pragma unroll
    for (int i = 0; i < 8; i++){
        int idx = t + i*NT;
        int row = idx >> 5, col8 = (idx & 31)*8;
        cpa16(Bsm + row*264 + col8, BsrcT + (size_t)(n0 + row)*256 + col8);
    }
    CPA_COMMIT(); CPA_WAIT0();
    __syncthreads();
}

// ---------- fp16 HMMA GEMM: 64(m) x 256(n), K=256; 32 warps, warp tile 16x32 ----------
__device__ void gemm_mma(const __half* __restrict__ Asrc,
                         const float* __restrict__ bias, float* __restrict__ outp,
                         int N, int m0, int n0, int mode, char* dyn,
                         float (*s_red)[8][2])
{
    const int t = threadIdx.x, w = t >> 5, lane = t & 31;
    const int wm = w & 3, wn = w >> 2;
    const int r4 = lane >> 2, q = lane & 3;

    __half* Asm = (__half*)(dyn + OFF_A);        // [64][264]
    const __half* Bsm = (const __half*)dyn;      // [256][264] persistent

    // stage A tile in two overlapping k-halves (1 cpa16/thread each)
    {
        int row = t >> 4, col8 = (t & 15)*8;
        cpa16(Asm + row*264 + col8, Asrc + (size_t)(m0 + row)*256 + col8);
        CPA_COMMIT();
        cpa16(Asm + row*264 + col8 + 128, Asrc + (size_t)(m0 + row)*256 + col8 + 128);
        CPA_COMMIT();
    }

    float acc[4][4];
    #pragma unroll
    for (int f = 0; f < 4; f++)
        #pragma unroll
        for (int rr = 0; rr < 4; rr++) acc[f][rr] = 0.f;

    const __half* Ab = Asm + (wm*16 + r4)*264 + 2*q;
    const __half* Bb = Bsm + (wn*32 + r4)*264 + 2*q;

    CPA_WAIT1();
    __syncthreads();
    #pragma unroll 4
    for (int ks = 0; ks < 8; ks++){
        const int kb = ks*16;
        unsigned a[4], bf[4][2];
        a[0] = *(const unsigned*)(Ab + kb);
        a[1] = *(const unsigned*)(Ab + 8*264 + kb);
        a[2] = *(const unsigned*)(Ab + kb + 8);
        a[3] = *(const unsigned*)(Ab + 8*264 + kb + 8);
        #pragma unroll
        for (int f = 0; f < 4; f++){
            const __half* Bf = Bb + f*8*264 + kb;
            bf[f][0] = *(const unsigned*)(Bf);
            bf[f][1] = *(const unsigned*)(Bf + 8);
        }
        #pragma unroll
        for (int f = 0; f < 4; f++) mma_f16(acc[f], a, bf[f]);
    }
    CPA_WAIT0();
    __syncthreads();
    #pragma unroll 4
    for (int ks = 8; ks < 16; ks++){
        const int kb = ks*16;
        unsigned a[4], bf[4][2];
        a[0] = *(const unsigned*)(Ab + kb);
        a[1] = *(const unsigned*)(Ab + 8*264 + kb);
        a[2] = *(const unsigned*)(Ab + kb + 8);
        a[3] = *(const unsigned*)(Ab + 8*264 + kb + 8);
        #pragma unroll
        for (int f = 0; f < 4; f++){
            const __half* Bf = Bb + f*8*264 + kb;
            bf[f][0] = *(const unsigned*)(Bf);
            bf[f][1] = *(const unsigned*)(Bf + 8);
        }
        #pragma unroll
        for (int f = 0; f < 4; f++) mma_f16(acc[f], a, bf[f]);
    }

    #pragma unroll
    for (int f = 0; f < 4; f++){
        float b0 = bias[n0 + wn*32 + f*8 + 2*q];
        float b1 = bias[n0 + wn*32 + f*8 + 2*q + 1];
        acc[f][0] += b0; acc[f][1] += b1;
        acc[f][2] += b0; acc[f][3] += b1;
    }

    if (mode == 1){
        #pragma unroll
        for (int h = 0; h < 2; h++){
            float s1 = 0.f, s2 = 0.f;
            #pragma unroll
            for (int f = 0; f < 4; f++){
                float v0 = acc[f][2*h], v1 = acc[f][2*h + 1];
                s1 += v0 + v1; s2 += v0*v0 + v1*v1;
            }
            s1 += __shfl_xor_sync(0xffffffffu, s1, 1);
            s2 += __shfl_xor_sync(0xffffffffu, s2, 1);
            s1 += __shfl_xor_sync(0xffffffffu, s1, 2);
            s2 += __shfl_xor_sync(0xffffffffu, s2, 2);
            if (q == 0){
                int rl = wm*16 + h*8 + r4;
                s_red[rl][wn][0] = s1; s_red[rl][wn][1] = s2;
            }
        }
        __syncthreads();
        __half* P = (__half*)(dyn + OFF_P);    // [256 d][72 i]
        #pragma unroll
        for (int h = 0; h < 2; h++){
            int rl = wm*16 + h*8 + r4;
            float t1 = 0.f, t2 = 0.f;
            #pragma unroll
            for (int j = 0; j < 8; j++){ t1 += s_red[rl][j][0]; t2 += s_red[rl][j][1]; }
            float mean = t1 * (1.f/256.f);
            float var  = t2 * (1.f/256.f) - mean*mean;
            float rstd = rsqrtf(var + 1e-5f);
            #pragma unroll
            for (int f = 0; f < 4; f++){
                float v0 = (acc[f][2*h]   - mean) * rstd;
                float v1 = (acc[f][2*h+1] - mean) * rstd;
                int colb = wn*32 + f*8 + 2*q;
                P[(size_t)(colb  )*72 + rl] = __float2half(v0);
                P[(size_t)(colb+1)*72 + rl] = __float2half(v1);
            }
        }
    } else {
        #pragma unroll
        for (int h = 0; h < 2; h++){
            int row = m0 + wm*16 + h*8 + r4;
            float* op = outp + (size_t)row*N + n0 + wn*32 + 2*q;
            #pragma unroll
            for (int f = 0; f < 4; f++){
                float2 o2; o2.x = acc[f][2*h]; o2.y = acc[f][2*h+1];
                *(float2*)(op + f*8) = o2;
            }
        }
    }
    __syncthreads();
}

// ---------- einsum A staging (once; loop-invariant) ----------
__device__ void stage_Ae(const float* __restrict__ A, int b, int r, char* dyn){
    __half* AsE = (__half*)(dyn + OFF_ASE);   // [64 j][72 i]
    const float* Ab = A + (size_t)b*32768 + r;
    const int t = threadIdx.x;
    #pragma unroll
    for (int pass = 0; pass < 4; pass++){
        int e = pass*NT + t;
        int j = e & 63, i = e >> 6;
        AsE[j*72 + i] = __float2half(Ab[(size_t)i*512 + j*8]);
    }
    __syncthreads();
}

// ---------- einsum (fp16 HMMA): 32 warps, warp tile 16(j) x 32(d), K=64 ----------
__device__ void einsum_mma(int b, int r, char* dyn)
{
    const int t = threadIdx.x, w = t >> 5, lane = t & 31;
    const int wm = w & 3, wn = w >> 2;
    const int r4 = lane >> 2, q = lane & 3;

    const __half* AsE = (const __half*)(dyn + OFF_ASE);
    const __half* P   = (const __half*)(dyn + OFF_P);

    float acc[4][4];
    #pragma unroll
    for (int f = 0; f < 4; f++)
        #pragma unroll
        for (int rr = 0; rr < 4; rr++) acc[f][rr] = 0.f;

    const __half* Ab = AsE + (wm*16 + r4)*72 + 2*q;
    const __half* Bb = P   + (wn*32 + r4)*72 + 2*q;
    #pragma unroll
    for (int ks = 0; ks < 4; ks++){
        const int kb = ks*16;
        unsigned a[4], bf[4][2];
        a[0] = *(const unsigned*)(Ab + kb);
        a[1] = *(const unsigned*)(Ab + 8*72 + kb);
        a[2] = *(const unsigned*)(Ab + kb + 8);
        a[3] = *(const unsigned*)(Ab + 8*72 + kb + 8);
        #pragma unroll
        for (int f = 0; f < 4; f++){
            const __half* Bf = Bb + f*8*72 + kb;
            bf[f][0] = *(const unsigned*)(Bf);
            bf[f][1] = *(const unsigned*)(Bf + 8);
        }
        #pragma unroll
        for (int f = 0; f < 4; f++) mma_f16(acc[f], a, bf[f]);
    }

    float* pb = g_part + (size_t)(b*8 + r)*64*256;
    #pragma unroll
    for (int h = 0; h < 2; h++){
        int j = wm*16 + h*8 + r4;
        float* op = pb + (size_t)j*256 + wn*32 + 2*q;
        #pragma unroll
        for (int f = 0; f < 4; f++){
            float2 o2; o2.x = acc[f][2*h]; o2.y = acc[f][2*h+1];
            *(float2*)(op + f*8) = o2;
        }
    }
}

// ---------- step phases 2+3 (32 warps) ----------
__device__ void step23(const float* __restrict__ bout, int iter, char* dyn)
{
    StepSm* sm = (StepSm*)(dyn + OFF_A);
    const int t  = threadIdx.x;
    const int b  = blockIdx.x >> 3;
    const int j0 = (blockIdx.x & 7) * 8;
    const int row0 = b*64 + j0;
    const int w = t >> 5, lane = t & 31;

    // phase 2: warp = (row r, d-quarter dq); 2 d values/thread
    {
        const int r  = w & 7;
        const int dq = w >> 3;
        const int j  = j0 + r;
        const float* iorow = g_io + (size_t)(row0 + r)*768;
        const float* pp = g_part + (size_t)(b*8)*64*256 + (size_t)j*256;
        float hv2[2];
        float s = 0.f, s2 = 0.f;
        #pragma unroll
        for (int qq = 0; qq < 2; qq++){
            int d = dq*64 + qq*32 + lane;
            float x = 0.f;
            #pragma unroll
            for (int rel = 0; rel < 8; rel++)
                x += pp[(size_t)rel*64*256 + d];
            x = x - tanhf(x);
            x += iorow[512 + d];
            hv2[qq] = x;
            s += x; s2 += x*x;
        }
        #pragma unroll
        for (int o = 16; o > 0; o >>= 1){
            s  += __shfl_xor_sync(0xffffffffu, s,  o);
            s2 += __shfl_xor_sync(0xffffffffu, s2, o);
        }
        if (lane == 0){ sm->lnp[r][dq][0] = s; sm->lnp[r][dq][1] = s2; }
        __syncthreads();
        float t1 = sm->lnp[r][0][0] + sm->lnp[r][1][0] + sm->lnp[r][2][0] + sm->lnp[r][3][0];
        float t2 = sm->lnp[r][0][1] + sm->lnp[r][1][1] + sm->lnp[r][2][1] + sm->lnp[r][3][1];
        float mean = t1 * (1.f/256.f);
        float var  = t2 * (1.f/256.f) - mean*mean;
        float rstd = rsqrtf(var + 1e-5f);
        #pragma unroll
        for (int qq = 0; qq < 2; qq++){
            int d = dq*64 + qq*32 + lane;
            float lnv = (hv2[qq]-mean)*rstd;
            float g = fmaf(iorow[d], lnv, iorow[256+d]);
            sm->hsmh[r][d] = __float2half(fmaxf(g, 0.f));
        }
    }
    __syncthreads();

    // phase 3: fp16 HMMA; warp w owns n8 = w*8 (8 cols), rows 0..7 live
    {
        const __half* hs = &sm->hsmh[0][0];
        const int n8 = w * 8;
        const int m  = lane >> 2;            // A row / B n-index
        const int kq = (lane & 3) * 2;
        float acc3[4] = {0.f, 0.f, 0.f, 0.f};

        #pragma unroll 4
        for (int ks = 0; ks < 16; ks++){
            const int kb = ks*16;
            unsigned a[4], bf[2];
            a[0] = *(const unsigned*)&hs[m*264 + kb + kq];
            a[2] = *(const unsigned*)&hs[m*264 + kb + kq + 8];
            a[1] = 0u; a[3] = 0u;
            const __half* wp = g_woH + (size_t)(n8 + m)*256 + kb + kq;
            bf[0] = *(const unsigned*)(wp);
            bf[1] = *(const unsigned*)(wp + 8);
            mma_f16(acc3, a, bf);
        }

        bool masked = (iter > g_len[b]);
        const int gr = row0 + m;
        int n = n8 + kq;
        float2 bo = *(const float2*)&bout[n];
        float y0 = masked ? 0.f : tanhf(acc3[0] + bo.x);
        float y1 = masked ? 0.f : tanhf(acc3[1] + bo.y);
        __half2 hy = __floats2half2_rn(y0, y1);
        *(unsigned*)&g_hh[(size_t)gr*256 + n] = *(unsigned*)&hy;
    }
}

// ---------- 64x64 weight tile transpose fp32 -> [n][k] half ----------
__device__ void transpose_w(const float* __restrict__ src, __half* __restrict__ dst,
                            int Nn, int tk, int tn, char* dyn)
{
    float (*ts)[65] = (float(*)[65])dyn;
    const int t = threadIdx.x;
    const int rr = t >> 6, cc = t & 63;
    #pragma unroll
    for (int pass = 0; pass < 4; pass++){
        int r = pass*16 + rr;
        ts[r][cc] = src[(size_t)(tk*64 + r)*Nn + tn*64 + cc];
    }
    __syncthreads();
    #pragma unroll
    for (int pass = 0; pass < 4; pass++){
        int r = pass*16 + rr;
        dst[(size_t)(tn*64 + r)*256 + tk*64 + cc] = __float2half(ts[cc][r]);
    }
    __syncthreads();
}

// ---------- single persistent kernel ----------
__global__ void __launch_bounds__(NT) fused_kernel(
    const int* __restrict__ tokens, const float* __restrict__ A,
    const float* __restrict__ root, const float* __restrict__ emb,
    const float* __restrict__ Wp,   const float* __restrict__ bp,
    const float* __restrict__ Win,  const float* __restrict__ bin,
    const float* __restrict__ Wout, const float* __restrict__ bout,
    float* __restrict__ out)
{
    extern __shared__ char smraw[];
    char* dyn = (char*)((((size_t)smraw) + 1023) & ~(size_t)1023);
    __shared__ float s_red[64][8][2];

    const int bid = blockIdx.x;
    const int t = threadIdx.x;
    const int b = bid >> 3, r = bid & 7;

    // prologue: gather (half), zero h, lengths
    {
        int idx = r*NT + t;                  // batch b: 4096 float4 slots
        if (idx < 4096){
            int l = idx >> 6;
            int c4 = (idx & 63) * 4;
            int row = b*64 + l;
            int tok = tokens[l*16 + b];
            float4 e4 = *(const float4*)&emb[(size_t)tok*256 + c4];
            __half2 h0 = __floats2half2_rn(e4.x, e4.y);
            __half2 h1 = __floats2half2_rn(e4.z, e4.w);
            uint2 u; u.x = *(unsigned*)&h0; u.y = *(unsigned*)&h1;
            *(uint2*)&g_xh[(size_t)row*256 + c4] = u;
            uint2 z; z.x = 0u; z.y = 0u;
            *(uint2*)&g_hh[(size_t)row*256 + c4] = z;
        }
        if (r == 0 && t == 0){
            int c = 0;
            for (int l2 = 0; l2 < 64; l2++) c += (tokens[l2*16 + b] != 0);
            g_len[b] = c;
        }
    }
    transpose_w(Wp, g_wpH, 2048, bid >> 5, bid & 31, dyn);       // 128 tiles
    if (bid < 48)
        transpose_w(Win, g_winH, 768, bid / 12, bid % 12, dyn);  // 48 tiles
    if (bid < 16)
        transpose_w(Wout, g_woH, 256, bid >> 2, bid & 3, dyn);   // 16 tiles
    grid_sync();

    // persistent einsum A
    stage_Ae(A, b, r, dyn);

    // hoisted in_proj (blocks r<3; Win slice staged into B region temporarily)
    if (r < 3){
        stage_B(g_winH, r*256, dyn);
        gemm_mma(g_xh, bin, g_io, 768, b*64, r*256, 0, dyn, s_red);
    }
    // persistent Wp slice for the recurrence
    stage_B(g_wpH, r*256, dyn);
    group_sync(b);

    // 64-step recurrence — batch-local
    for (int it = 0; it < 64; it++){
        gemm_mma(g_hh, bp, (float*)0, 2048, b*64, r*256, 1, dyn, s_red);
        einsum_mma(b, r, dyn);
        group_sync(b);
        step23(bout, 64 - it, dyn);
        group_sync(b);
    }

    // epilogue: out[b][d] = sum_i h[b,i,d] * root[b,i]
    if (r == 0 && t < 256){
        float s = 0.f;
        #pragma unroll 8
        for (int i = 0; i < 64; i++)
            s += __half2float(g_hh[(size_t)(b*64 + i)*256 + t]) * root[b*64 + i];
        out[b*256 + t] = s;
    }
}

extern "C" void kernel_launch(void* const* d_in, const int* in_sizes, int n_in,
                              void* d_out, int out_size)
{
    const int*   tokens = (const int*)  d_in[0];
    const float* A      = (const float*)d_in[1];
    const float* root   = (const float*)d_in[2];
    const float* emb    = (const float*)d_in[3];
    const float* Wp     = (const float*)d_in[4];
    const float* bp     = (const float*)d_in[5];
    const float* Win    = (const float*)d_in[6];
    const float* bin    = (const float*)d_in[7];
    const float* Wout   = (const float*)d_in[8];
    const float* bout   = (const float*)d_in[9];

    cudaFuncSetAttribute(fused_kernel, cudaFuncAttributeMaxDynamicSharedMemorySize, SMEM_DYN);
    fused_kernel<<<NBLOCKS, NT, SMEM_DYN>>>(tokens, A, root, emb, Wp, bp, Win, bin,
                                            Wout, bout, (float*)d_out);
}

// round 17
// speedup vs baseline: 1.3327x; 1.3327x over previous
#include <cuda_runtime.h>
#include <cuda_fp16.h>

#define NBLOCKS 128
typedef unsigned long long ull;

__device__ __align__(16) __half g_xh [1024*256];     // gathered embeddings (half)
__device__ __align__(16) float  g_io [1024*768];     // shift|scale|proj_x (fp32)
__device__ __align__(16) float  g_part[16*8*64*256]; // [b][rel][j][d] partial lin_sum
__device__ __align__(16) __half g_hh [1024*256];     // recurrent state (half)
__device__ __align__(16) __half g_wpH [2048*256];    // Wp  transposed [n][k] half
__device__ __align__(16) __half g_winH[768*256];     // Win transposed [n][k] half
__device__ __align__(16) uint2  g_woP [16*16*2*32];  // Wout fragment-permuted [w][ks][fr][lane]
__device__ int g_len[16];
__device__ unsigned g_cnt = 0, g_gen = 0;
__device__ unsigned g_gcnt[16*32];
__device__ unsigned g_ggen[16*32];

// ---------- helpers ----------
__device__ __forceinline__ void cpa16(void* s, const void* g){
    unsigned ss = (unsigned)__cvta_generic_to_shared(s);
    asm volatile("cp.async.cg.shared.global [%0], [%1], 16;\n" :: "r"(ss), "l"(g));
}
#define CPA_COMMIT() asm volatile("cp.async.commit_group;\n" ::: "memory")
#define CPA_WAIT0()  asm volatile("cp.async.wait_group 0;\n" ::: "memory")
#define CPA_WAIT1()  asm volatile("cp.async.wait_group 1;\n" ::: "memory")

// legacy HMMA m16n8k16 fp16, fp32 accumulate (base sm_103-legal)
__device__ __forceinline__ void mma_f16(float* d, const unsigned* a, const unsigned* b){
    asm volatile(
        "mma.sync.aligned.m16n8k16.row.col.f32.f16.f16.f32 "
        "{%0,%1,%2,%3}, {%4,%5,%6,%7}, {%8,%9}, {%0,%1,%2,%3};"
        : "+f"(d[0]), "+f"(d[1]), "+f"(d[2]), "+f"(d[3])
        : "r"(a[0]), "r"(a[1]), "r"(a[2]), "r"(a[3]), "r"(b[0]), "r"(b[1]));
}

// ---------- dynamic smem layout (bytes) ----------
// [0,135168)        B persistent half[256 n][264 k]
// [135168,168960)   A tile half[64 m][264 k]  | StepSm
// [168960,205824)   P half[256 d][72 i]
// [205824,215040)   AsE half[64 j][72 i]
#define OFF_A    135168
#define OFF_P    168960
#define OFF_ASE  205824
#define SMEM_DYN 215040
struct StepSm { __half hsmh[16][264]; float lnp[8][2][2]; };

// ---------- lightweight acq/rel barriers ----------
__device__ __forceinline__ void bar_lite(unsigned* cnt, unsigned* gen, unsigned last){
    __syncthreads();
    if (threadIdx.x == 0){
        unsigned my, old;
        asm volatile("ld.relaxed.gpu.u32 %0, [%1];" : "=r"(my) : "l"(gen) : "memory");
        asm volatile("atom.add.acq_rel.gpu.u32 %0, [%1], 1;" : "=r"(old) : "l"(cnt) : "memory");
        if (old == last){
            asm volatile("st.relaxed.gpu.u32 [%0], 0;" :: "l"(cnt) : "memory");
            unsigned du;
            asm volatile("atom.add.release.gpu.u32 %0, [%1], 1;" : "=r"(du) : "l"(gen) : "memory");
        } else {
            unsigned v;
            do {
                asm volatile("ld.acquire.gpu.u32 %0, [%1];" : "=r"(v) : "l"(gen) : "memory");
            } while (v == my);
        }
        __threadfence();   // CCTL.IVALL — invalidate this SM's L1D
    }
    __syncthreads();
}
__device__ __forceinline__ void grid_sync(){ bar_lite(&g_cnt, &g_gen, NBLOCKS - 1u); }
__device__ __forceinline__ void group_sync(int b){ bar_lite(&g_gcnt[b*32], &g_ggen[b*32], 7u); }

// ---------- stage persistent B slice (256 n x 256 k half) ----------
__device__ void stage_B(const __half* __restrict__ BsrcT, int n0, char* dyn){
    __half* Bsm = (__half*)dyn;
    const int t = threadIdx.x;
    #pragma unroll
    for (int i = 0; i < 16; i++){
        int idx = t + i*512;
        int row = idx >> 5, col8 = (idx & 31)*8;
        cpa16(Bsm + row*264 + col8, BsrcT + (size_t)(n0 + row)*256 + col8);
    }
    CPA_COMMIT(); CPA_WAIT0();
    __syncthreads();
}

// ---------- fp16 HMMA GEMM: 64(m) x 256(n), K=256; B persistent ----------
__device__ void gemm_mma(const __half* __restrict__ Asrc,
                         const float* __restrict__ bias, float* __restrict__ outp,
                         int N, int m0, int n0, int mode, char* dyn,
                         float (*s_red)[8][2])
{
    const int t = threadIdx.x, w = t >> 5, lane = t & 31;
    const int wm = w & 1, wn = w >> 1;
    const int r4 = lane >> 2, q = lane & 3;

    __half* Asm = (__half*)(dyn + OFF_A);        // [64][264]
    const __half* Bsm = (const __half*)dyn;      // [256][264] persistent

    // stage A tile in two overlapping k-halves
    #pragma unroll
    for (int i = 0; i < 2; i++){
        int idx = t + i*512;
        int row = idx >> 4, col8 = (idx & 15)*8;
        cpa16(Asm + row*264 + col8, Asrc + (size_t)(m0 + row)*256 + col8);
    }
    CPA_COMMIT();
    #pragma unroll
    for (int i = 0; i < 2; i++){
        int idx = t + i*512;
        int row = idx >> 4, col8 = (idx & 15)*8 + 128;
        cpa16(Asm + row*264 + col8, Asrc + (size_t)(m0 + row)*256 + col8);
    }
    CPA_COMMIT();

    float acc[2][4][4];
    #pragma unroll
    for (int g = 0; g < 2; g++)
        #pragma unroll
        for (int f = 0; f < 4; f++)
            #pragma unroll
            for (int rr = 0; rr < 4; rr++) acc[g][f][rr] = 0.f;

    const __half* Ab = Asm + (wm*32 + r4)*264 + 2*q;
    const __half* Bb = Bsm + (wn*32 + r4)*264 + 2*q;

    CPA_WAIT1();
    __syncthreads();
    #pragma unroll 4
    for (int ks = 0; ks < 8; ks++){
        const int kb = ks*16;
        unsigned a[2][4], bf[4][2];
        #pragma unroll
        for (int g = 0; g < 2; g++){
            const __half* Ag = Ab + g*16*264 + kb;
            a[g][0] = *(const unsigned*)(Ag);
            a[g][1] = *(const unsigned*)(Ag + 8*264);
            a[g][2] = *(const unsigned*)(Ag + 8);
            a[g][3] = *(const unsigned*)(Ag + 8*264 + 8);
        }
        #pragma unroll
        for (int f = 0; f < 4; f++){
            const __half* Bf = Bb + f*8*264 + kb;
            bf[f][0] = *(const unsigned*)(Bf);
            bf[f][1] = *(const unsigned*)(Bf + 8);
        }
        #pragma unroll
        for (int g = 0; g < 2; g++)
            #pragma unroll
            for (int f = 0; f < 4; f++)
                mma_f16(acc[g][f], a[g], bf[f]);
    }
    CPA_WAIT0();
    __syncthreads();
    #pragma unroll 4
    for (int ks = 8; ks < 16; ks++){
        const int kb = ks*16;
        unsigned a[2][4], bf[4][2];
        #pragma unroll
        for (int g = 0; g < 2; g++){
            const __half* Ag = Ab + g*16*264 + kb;
            a[g][0] = *(const unsigned*)(Ag);
            a[g][1] = *(const unsigned*)(Ag + 8*264);
            a[g][2] = *(const unsigned*)(Ag + 8);
            a[g][3] = *(const unsigned*)(Ag + 8*264 + 8);
        }
        #pragma unroll
        for (int f = 0; f < 4; f++){
            const __half* Bf = Bb + f*8*264 + kb;
            bf[f][0] = *(const unsigned*)(Bf);
            bf[f][1] = *(const unsigned*)(Bf + 8);
        }
        #pragma unroll
        for (int g = 0; g < 2; g++)
            #pragma unroll
            for (int f = 0; f < 4; f++)
                mma_f16(acc[g][f], a[g], bf[f]);
    }

    #pragma unroll
    for (int f = 0; f < 4; f++){
        float b0 = bias[n0 + wn*32 + f*8 + 2*q];
        float b1 = bias[n0 + wn*32 + f*8 + 2*q + 1];
        #pragma unroll
        for (int g = 0; g < 2; g++){
            acc[g][f][0] += b0; acc[g][f][1] += b1;
            acc[g][f][2] += b0; acc[g][f][3] += b1;
        }
    }

    if (mode == 1){
        #pragma unroll
        for (int g = 0; g < 2; g++)
            #pragma unroll
            for (int h = 0; h < 2; h++){
                float s1 = 0.f, s2 = 0.f;
                #pragma unroll
                for (int f = 0; f < 4; f++){
                    float v0 = acc[g][f][2*h], v1 = acc[g][f][2*h + 1];
                    s1 += v0 + v1; s2 += v0*v0 + v1*v1;
                }
                s1 += __shfl_xor_sync(0xffffffffu, s1, 1);
                s2 += __shfl_xor_sync(0xffffffffu, s2, 1);
                s1 += __shfl_xor_sync(0xffffffffu, s1, 2);
                s2 += __shfl_xor_sync(0xffffffffu, s2, 2);
                if (q == 0){
                    int rl = wm*32 + g*16 + h*8 + r4;
                    s_red[rl][wn][0] = s1; s_red[rl][wn][1] = s2;
                }
            }
        __syncthreads();
        __half* P = (__half*)(dyn + OFF_P);    // [256 d][72 i]
        #pragma unroll
        for (int g = 0; g < 2; g++)
            #pragma unroll
            for (int h = 0; h < 2; h++){
                int rl = wm*32 + g*16 + h*8 + r4;
                float t1 = 0.f, t2 = 0.f;
                #pragma unroll
                for (int j = 0; j < 8; j++){ t1 += s_red[rl][j][0]; t2 += s_red[rl][j][1]; }
                float mean = t1 * (1.f/256.f);
                float var  = t2 * (1.f/256.f) - mean*mean;
                float rstd = rsqrtf(var + 1e-5f);
                #pragma unroll
                for (int f = 0; f < 4; f++){
                    float v0 = (acc[g][f][2*h]   - mean) * rstd;
                    float v1 = (acc[g][f][2*h+1] - mean) * rstd;
                    int colb = wn*32 + f*8 + 2*q;
                    P[(size_t)(colb  )*72 + rl] = __float2half(v0);
                    P[(size_t)(colb+1)*72 + rl] = __float2half(v1);
                }
            }
    } else {
        #pragma unroll
        for (int g = 0; g < 2; g++)
            #pragma unroll
            for (int h = 0; h < 2; h++){
                int row = m0 + wm*32 + g*16 + h*8 + r4;
                float* op = outp + (size_t)row*N + n0 + wn*32 + 2*q;
                #pragma unroll
                for (int f = 0; f < 4; f++){
                    float2 o2; o2.x = acc[g][f][2*h]; o2.y = acc[g][f][2*h+1];
                    *(float2*)(op + f*8) = o2;
                }
            }
    }
    __syncthreads();
}

// ---------- einsum A staging (once; loop-invariant) ----------
__device__ void stage_Ae(const float* __restrict__ A, int b, int r, char* dyn){
    __half* AsE = (__half*)(dyn + OFF_ASE);   // [64 j][72 i]
    const float* Ab = A + (size_t)b*32768 + r;
    const int t = threadIdx.x;
    #pragma unroll
    for (int pass = 0; pass < 8; pass++){
        int e = pass*512 + t;
        int j = e & 63, i = e >> 6;
        AsE[j*72 + i] = __float2half(Ab[(size_t)i*512 + j*8]);
    }
    __syncthreads();
}

// ---------- einsum (fp16 HMMA): partial[j][d] = sum_i A[b,i,j,r]*p_r[i][d] ----------
__device__ void einsum_mma(int b, int r, char* dyn)
{
    const int t = threadIdx.x, w = t >> 5, lane = t & 31;
    const int wm = w & 1, wn = w >> 1;
    const int r4 = lane >> 2, q = lane & 3;

    const __half* AsE = (const __half*)(dyn + OFF_ASE);
    const __half* P   = (const __half*)(dyn + OFF_P);

    float acc[2][4][4];
    #pragma unroll
    for (int g = 0; g < 2; g++)
        #pragma unroll
        for (int f = 0; f < 4; f++)
            #pragma unroll
            for (int rr = 0; rr < 4; rr++) acc[g][f][rr] = 0.f;

    const __half* Ab = AsE + (wm*32 + r4)*72 + 2*q;
    const __half* Bb = P   + (wn*32 + r4)*72 + 2*q;
    #pragma unroll
    for (int ks = 0; ks < 4; ks++){
        const int kb = ks*16;
        unsigned a[2][4], bf[4][2];
        #pragma unroll
        for (int g = 0; g < 2; g++){
            const __half* Ag = Ab + g*16*72 + kb;
            a[g][0] = *(const unsigned*)(Ag);
            a[g][1] = *(const unsigned*)(Ag + 576);
            a[g][2] = *(const unsigned*)(Ag + 8);
            a[g][3] = *(const unsigned*)(Ag + 584);
        }
        #pragma unroll
        for (int f = 0; f < 4; f++){
            const __half* Bf = Bb + f*8*72 + kb;
            bf[f][0] = *(const unsigned*)(Bf);
            bf[f][1] = *(const unsigned*)(Bf + 8);
        }
        #pragma unroll
        for (int g = 0; g < 2; g++)
            #pragma unroll
            for (int f = 0; f < 4; f++)
                mma_f16(acc[g][f], a[g], bf[f]);
    }

    float* pb = g_part + (size_t)(b*8 + r)*64*256;
    #pragma unroll
    for (int g = 0; g < 2; g++)
        #pragma unroll
        for (int h = 0; h < 2; h++){
            int j = wm*32 + g*16 + h*8 + r4;
            float* op = pb + (size_t)j*256 + wn*32 + 2*q;
            #pragma unroll
            for (int f = 0; f < 4; f++){
                float2 o2; o2.x = acc[g][f][2*h]; o2.y = acc[g][f][2*h+1];
                *(float2*)(op + f*8) = o2;
            }
        }
}

// ---------- step phases 2+3 ----------
__device__ void step23(const float* __restrict__ bout, int iter, char* dyn)
{
    StepSm* sm = (StepSm*)(dyn + OFF_A);
    const int t  = threadIdx.x;
    const int b  = blockIdx.x >> 3;
    const int j0 = (blockIdx.x & 7) * 8;
    const int row0 = b*64 + j0;
    const int w = t >> 5, lane = t & 31;

    // phase 2
    {
        const int r  = w & 7;
        const int dh = w >> 3;
        const int j  = j0 + r;
        const float* iorow = g_io + (size_t)(row0 + r)*768;
        const float* pp = g_part + (size_t)(b*8)*64*256 + (size_t)j*256;
        float hv2[4];
        float s = 0.f, s2 = 0.f;
        #pragma unroll
        for (int qq = 0; qq < 4; qq++){
            int d = dh*128 + qq*32 + lane;
            float x = 0.f;
            #pragma unroll
            for (int rel = 0; rel < 8; rel++)
                x += pp[(size_t)rel*64*256 + d];
            x = x - tanhf(x);
            x += iorow[512 + d];
            hv2[qq] = x;
            s += x; s2 += x*x;
        }
        #pragma unroll
        for (int o = 16; o > 0; o >>= 1){
            s  += __shfl_xor_sync(0xffffffffu, s,  o);
            s2 += __shfl_xor_sync(0xffffffffu, s2, o);
        }
        if (lane == 0){ sm->lnp[r][dh][0] = s; sm->lnp[r][dh][1] = s2; }
        __syncthreads();
        float t1 = sm->lnp[r][0][0] + sm->lnp[r][1][0];
        float t2 = sm->lnp[r][0][1] + sm->lnp[r][1][1];
        float mean = t1 * (1.f/256.f);
        float var  = t2 * (1.f/256.f) - mean*mean;
        float rstd = rsqrtf(var + 1e-5f);
        #pragma unroll
        for (int qq = 0; qq < 4; qq++){
            int d = dh*128 + qq*32 + lane;
            float lnv = (hv2[qq]-mean)*rstd;
            float g = fmaf(iorow[d], lnv, iorow[256+d]);
            sm->hsmh[r][d] = __float2half(fmaxf(g, 0.f));
        }
    }
    __syncthreads();

    // phase 3: fp16 HMMA with fragment-permuted Wout (coalesced LDG.64)
    {
        const __half* hs = &sm->hsmh[0][0];
        const int m  = lane >> 2;            // row 0..7 (rows 8..15 zeroed)
        const int kq = (lane & 3) * 2;
        float acc3[2][4];
        #pragma unroll
        for (int fr = 0; fr < 2; fr++)
            #pragma unroll
            for (int rr = 0; rr < 4; rr++) acc3[fr][rr] = 0.f;

        const uint2* wperm = g_woP + ((size_t)w*16)*2*32 + lane;
        #pragma unroll 4
        for (int ks = 0; ks < 16; ks++){
            const int kb = ks*16;
            unsigned a[4];
            a[0] = *(const unsigned*)&hs[m*264 + kb + kq];
            a[2] = *(const unsigned*)&hs[m*264 + kb + kq + 8];
            a[1] = 0u; a[3] = 0u;
            uint2 b0 = wperm[(ks*2    )*32];
            uint2 b1 = wperm[(ks*2 + 1)*32];
            mma_f16(acc3[0], a, (const unsigned*)&b0);
            mma_f16(acc3[1], a, (const unsigned*)&b1);
        }

        bool masked = (iter > g_len[b]);
        const int gr = row0 + m;
        const int n16 = w * 16;
        #pragma unroll
        for (int fr = 0; fr < 2; fr++){
            int n = n16 + fr*8 + kq;
            float2 bo = *(const float2*)&bout[n];
            float y0 = masked ? 0.f : tanhf(acc3[fr][0] + bo.x);
            float y1 = masked ? 0.f : tanhf(acc3[fr][1] + bo.y);
            __half2 hy = __floats2half2_rn(y0, y1);
            *(unsigned*)&g_hh[(size_t)gr*256 + n] = *(unsigned*)&hy;
        }
    }
}

// ---------- 64x64 weight tile transpose fp32 -> [n][k] half ----------
__device__ void transpose_w(const float* __restrict__ src, __half* __restrict__ dst,
                            int Nn, int tk, int tn, char* dyn)
{
    float (*ts)[65] = (float(*)[65])dyn;
    const int t = threadIdx.x;
    const int rr = t >> 6, cc = t & 63;
    #pragma unroll
    for (int pass = 0; pass < 8; pass++){
        int r = pass*8 + rr;
        ts[r][cc] = src[(size_t)(tk*64 + r)*Nn + tn*64 + cc];
    }
    __syncthreads();
    #pragma unroll
    for (int pass = 0; pass < 8; pass++){
        int r = pass*8 + rr;
        dst[(size_t)(tn*64 + r)*256 + tk*64 + cc] = __float2half(ts[cc][r]);
    }
    __syncthreads();
}

// ---------- single persistent kernel ----------
__global__ void __launch_bounds__(512) fused_kernel(
    const int* __restrict__ tokens, const float* __restrict__ A,
    const float* __restrict__ root, const float* __restrict__ emb,
    const float* __restrict__ Wp,   const float* __restrict__ bp,
    const float* __restrict__ Win,  const float* __restrict__ bin,
    const float* __restrict__ Wout, const float* __restrict__ bout,
    float* __restrict__ out)
{
    extern __shared__ char smraw[];
    char* dyn = (char*)((((size_t)smraw) + 1023) & ~(size_t)1023);
    __shared__ float s_red[64][8][2];

    const int bid = blockIdx.x;
    const int t = threadIdx.x;
    const int b = bid >> 3, r = bid & 7;

    // prologue: gather (half), zero h, lengths, Wout fragment permutation
    {
        int idx = r*512 + t;
        int l = idx >> 6;
        int c4 = (idx & 63) * 4;
        int row = b*64 + l;
        int tok = tokens[l*16 + b];
        float4 e4 = *(const float4*)&emb[(size_t)tok*256 + c4];
        __half2 h0 = __floats2half2_rn(e4.x, e4.y);
        __half2 h1 = __floats2half2_rn(e4.z, e4.w);
        uint2 u; u.x = *(unsigned*)&h0; u.y = *(unsigned*)&h1;
        *(uint2*)&g_xh[(size_t)row*256 + c4] = u;
        uint2 z; z.x = 0u; z.y = 0u;
        *(uint2*)&g_hh[(size_t)row*256 + c4] = z;
        if (r == 0 && t == 0){
            int c = 0;
            for (int l2 = 0; l2 < 64; l2++) c += (tokens[l2*16 + b] != 0);
            g_len[b] = c;
        }
        // Wout fragment-permuted fill: 32768 uint words total
        int e = bid*512 + t;
        if (e < 32768){
            int wd   = e & 1;
            int lanE = (e >> 1) & 31;
            int fr   = (e >> 6) & 1;
            int ks   = (e >> 7) & 15;
            int ww   = (e >> 11) & 15;
            int m  = lanE >> 2, kq = (lanE & 3) * 2;
            int n  = ww*16 + fr*8 + m;
            int k  = ks*16 + kq + wd*8;
            __half2 hv = __floats2half2_rn(Wout[(size_t)k*256 + n],
                                           Wout[(size_t)(k+1)*256 + n]);
            ((unsigned*)g_woP)[(((size_t)ww*16 + ks)*2 + fr)*64 + lanE*2 + wd] = *(unsigned*)&hv;
        }
    }
    transpose_w(Wp, g_wpH, 2048, bid >> 5, bid & 31, dyn);       // 128 tiles
    if (bid < 48)
        transpose_w(Win, g_winH, 768, bid / 12, bid % 12, dyn);  // 48 tiles
    grid_sync();

    // persistent einsum A
    stage_Ae(A, b, r, dyn);

    // hoisted in_proj (blocks r<3; Win slice staged into B region temporarily)
    if (r < 3){
        stage_B(g_winH, r*256, dyn);
        gemm_mma(g_xh, bin, g_io, 768, b*64, r*256, 0, dyn, s_red);
    }
    // persistent Wp slice for the recurrence
    stage_B(g_wpH, r*256, dyn);
    group_sync(b);

    // 64-step recurrence — batch-local
    for (int it = 0; it < 64; it++){
        gemm_mma(g_hh, bp, (float*)0, 2048, b*64, r*256, 1, dyn, s_red);
        einsum_mma(b, r, dyn);
        group_sync(b);
        step23(bout, 64 - it, dyn);
        group_sync(b);
    }

    // epilogue: out[b][d] = sum_i h[b,i,d] * root[b,i]
    if (r == 0 && t < 256){
        float s = 0.f;
        #pragma unroll 8
        for (int i = 0; i < 64; i++)
            s += __half2float(g_hh[(size_t)(b*64 + i)*256 + t]) * root[b*64 + i];
        out[b*256 + t] = s;
    }
}

extern "C" void kernel_launch(void* const* d_in, const int* in_sizes, int n_in,
                              void* d_out, int out_size)
{
    const int*   tokens = (const int*)  d_in[0];
    const float* A      = (const float*)d_in[1];
    const float* root   = (const float*)d_in[2];
    const float* emb    = (const float*)d_in[3];
    const float* Wp     = (const float*)d_in[4];
    const float* bp     = (const float*)d_in[5];
    const float* Win    = (const float*)d_in[6];
    const float* bin    = (const float*)d_in[7];
    const float* Wout   = (const float*)d_in[8];
    const float* bout   = (const float*)d_in[9];

    cudaFuncSetAttribute(fused_kernel, cudaFuncAttributeMaxDynamicSharedMemorySize, SMEM_DYN);
    fused_kernel<<<NBLOCKS, 512, SMEM_DYN>>>(tokens, A, root, emb, Wp, bp, Win, bin,
                                             Wout, bout, (float*)d_out);
}